// round 17
// baseline (speedup 1.0000x reference)
#include <cuda_runtime.h>
#include <cuda_fp16.h>
#include <cstdint>

// ============================================================================
// Problem constants
// ============================================================================
#define DK 4096            // D_IN  (K)
#define DN 4096            // D_OUT (N)
#define DM 4096            // B*S   (M)
#define NELEM_W (16777216) // 4096*4096

// ============================================================================
// Scratch (device globals — no allocations allowed)
// ============================================================================
__device__ long long g_part[256];                      // per-block partial sums of |wf|
__device__ long long g_mean_abs;                       // final weight scale
__device__ __half g_B  [(size_t)DN * DK];              // ternary weights as fp16
__device__ __half g_Alo[(size_t)DM * DK];              // low  limb of xq  [-1024,1023]
__device__ __half g_Ahi[(size_t)DM * DK];              // high limb of xq  (q-lo)>>11

// ============================================================================
// PTX helpers (base-target only: cp.async / ldmatrix / mma.sync)
// ============================================================================
__device__ __forceinline__ uint32_t smem_to_u32(const void* p) {
    uint32_t a;
    asm("{ .reg .u64 t; cvta.to.shared.u64 t, %1; cvt.u32.u64 %0, t; }" : "=r"(a) : "l"(p));
    return a;
}
__device__ __forceinline__ void cp_async16(uint32_t smaddr, const void* gptr) {
    asm volatile("cp.async.cg.shared.global [%0], [%1], 16;" :: "r"(smaddr), "l"(gptr));
}
__device__ __forceinline__ void cp_commit() {
    asm volatile("cp.async.commit_group;");
}
template <int N>
__device__ __forceinline__ void cp_wait() {
    asm volatile("cp.async.wait_group %0;" :: "n"(N));
}
__device__ __forceinline__ void ldsm_x4(uint32_t (&r)[4], uint32_t addr) {
    asm volatile("ldmatrix.sync.aligned.m8n8.x4.shared.b16 {%0,%1,%2,%3}, [%4];"
        : "=r"(r[0]), "=r"(r[1]), "=r"(r[2]), "=r"(r[3]) : "r"(addr));
}
__device__ __forceinline__ void mma_16816(float (&c)[4], const uint32_t (&a)[4],
                                          const uint32_t* b) {
    asm volatile(
        "mma.sync.aligned.m16n8k16.row.col.f32.f16.f16.f32 "
        "{%0,%1,%2,%3}, {%4,%5,%6,%7}, {%8,%9}, {%0,%1,%2,%3};"
        : "+f"(c[0]), "+f"(c[1]), "+f"(c[2]), "+f"(c[3])
        : "r"(a[0]), "r"(a[1]), "r"(a[2]), "r"(a[3]), "r"(b[0]), "r"(b[1]));
}

// ============================================================================
// Launch 1: per-block partial sums of |round(w*2^16)|
// ============================================================================
__global__ void reduce_partial_kernel(const float* __restrict__ w) {
    const float4* w4 = reinterpret_cast<const float4*>(w);
    long long s = 0;
    int base = blockIdx.x * 16384 + threadIdx.x;      // float4 index
    #pragma unroll 4
    for (int j = 0; j < 64; j++) {
        float4 f = w4[base + j * 256];
        #pragma unroll
        for (int u = 0; u < 4; u++) {
            int v = __float2int_rn((&f.x)[u] * 65536.0f);
            s += abs(v);
        }
    }
    #pragma unroll
    for (int o = 16; o > 0; o >>= 1) s += __shfl_down_sync(0xffffffffu, s, o);
    __shared__ long long ws[8];
    if ((threadIdx.x & 31) == 0) ws[threadIdx.x >> 5] = s;
    __syncthreads();
    if (threadIdx.x < 8) {
        s = ws[threadIdx.x];
        #pragma unroll
        for (int o = 4; o > 0; o >>= 1) s += __shfl_down_sync(0xffu, s, o);
        if (threadIdx.x == 0) g_part[blockIdx.x] = s;
    }
}

// ============================================================================
// Launch 2: per-row activation quant (exact Q16.16) + 2-limb radix-2048 split
// ============================================================================
__global__ void actquant_kernel(const float* __restrict__ x) {
    int r = blockIdx.x;
    int tid = threadIdx.x;
    const float4* x4 = reinterpret_cast<const float4*>(x + (size_t)r * DK) + tid * 4;

    int v[16];
    int mymax = 0;
    #pragma unroll
    for (int j = 0; j < 4; j++) {
        float4 f = x4[j];
        #pragma unroll
        for (int u = 0; u < 4; u++) {
            int q = __float2int_rn((&f.x)[u] * 65536.0f);   // RNE == jnp.round
            v[j * 4 + u] = q;
            mymax = max(mymax, abs(q));
        }
    }
    #pragma unroll
    for (int o = 16; o > 0; o >>= 1)
        mymax = max(mymax, __shfl_xor_sync(0xffffffffu, mymax, o));
    __shared__ int wmax[8];
    if ((tid & 31) == 0) wmax[tid >> 5] = mymax;
    __syncthreads();
    int bm = 0;
    #pragma unroll
    for (int j = 0; j < 8; j++) bm = max(bm, wmax[j]);

    long long maxv = bm < 1 ? 1 : bm;
    long long scale     = ((long long)127 << 32) / maxv;   // (127<<16<<16)//maxv
    long long scale_inv = ((long long)1 << 32) / scale;    // 2^32 // scale

    __half hlo[16], hhi[16];
    #pragma unroll
    for (int i = 0; i < 16; i++) {
        long long xs = ((long long)v[i] * scale) >> 16;    // arith shift == floor
        if (xs >  8323072ll) xs =  8323072ll;              //  127<<16
        if (xs < -8388608ll) xs = -8388608ll;              // -(128<<16)
        int q  = (int)((xs * scale_inv) >> 16);
        int lo = ((q + 1024) & 2047) - 1024;               // balanced mod 2048
        int hi = (q - lo) >> 11;                           // |hi| small: exact fp16
        hlo[i] = __int2half_rn(lo);
        hhi[i] = __int2half_rn(hi);
    }
    size_t o = (size_t)r * DK + tid * 16;
    *reinterpret_cast<uint4*>(&g_Alo[o])     = reinterpret_cast<uint4*>(hlo)[0];
    *reinterpret_cast<uint4*>(&g_Alo[o + 8]) = reinterpret_cast<uint4*>(hlo)[1];
    *reinterpret_cast<uint4*>(&g_Ahi[o])     = reinterpret_cast<uint4*>(hhi)[0];
    *reinterpret_cast<uint4*>(&g_Ahi[o + 8]) = reinterpret_cast<uint4*>(hhi)[1];
}

// ============================================================================
// Launch 3: combine partials -> mean_abs; ternarize weights -> fp16 {-1,0,1}
// ============================================================================
__global__ void ternary_kernel(const float* __restrict__ w) {
    __shared__ long long red[256];
    red[threadIdx.x] = g_part[threadIdx.x];
    __syncthreads();
    #pragma unroll
    for (int s = 128; s > 0; s >>= 1) {
        if (threadIdx.x < s) red[threadIdx.x] += red[threadIdx.x + s];
        __syncthreads();
    }
    long long mean_abs = red[0] >> 24;                  // // 2^24 elements
    if (mean_abs < 1) mean_abs = 1;
    if (blockIdx.x == 0 && threadIdx.x == 0) g_mean_abs = mean_abs;

    size_t i = ((size_t)blockIdx.x * blockDim.x + threadIdx.x) * 4;
    float4 f = *reinterpret_cast<const float4*>(w + i);
    __half h[4];
    #pragma unroll
    for (int u = 0; u < 4; u++) {
        long long wf = llrintf((&f.x)[u] * 65536.0f);
        int t = (wf >= mean_abs) ? 1 : ((wf < 0) ? -1 : 0);
        h[u] = __int2half_rn(t);
    }
    *reinterpret_cast<uint2*>(&g_B[i]) = *reinterpret_cast<uint2*>(h);
}

// ============================================================================
// Launch 4 (profiled): fp16 mma.sync GEMM, 2 CTAs per SM.
//   CTA tile 128(M) x 64(N), 256 threads (8 warps, 4x2), warp tile 32x32,
//   dual fp32 accumulators (lo & hi limb, exact integer sums < 2^24).
//   2-stage cp.async pipeline, K-chunk = 64 halves, 144B row pitch
//   (conflict-free ldmatrix). ~115 regs + 90KB smem -> 2 resident CTAs/SM:
//   when one CTA stalls at its chunk barrier / ldsm shadow, the other CTA's
//   HMMA stream keeps the tensor pipe busy (R8/R9/R13/R16 all pinned at
//   ~54-57% tensor with 1 CTA/SM regardless of intra-CTA schedule).
//   Stage rows: [0,128) Alo, [128,256) Ahi, [256,320) B.  Stage = 46080 B.
// ============================================================================
static constexpr int ROWP    = 144;                 // bytes per 64-half row (padded)
static constexpr int STAGE_B = 320 * ROWP;          // 46080 B
static constexpr int NSTAGE  = 2;
static constexpr int SMEM_SZ = NSTAGE * STAGE_B;    // 92160 B  (x2 CTAs = 184320)
static constexpr int NCHUNK  = DK / 64;             // 64

__device__ __forceinline__ void issue_chunk_loads(
    uint32_t sb, uint32_t soff,
    const __half* pAlo, const __half* pAhi, const __half* pB)
{
    // 256 threads: r0 = tid>>3 (0..31), seg = tid&7. Covers:
    //   Alo rows r0+32t (t=0..3), Ahi rows r0+32t, B rows r0, r0+32.
    #pragma unroll
    for (int t = 0; t < 4; t++)
        cp_async16(sb + soff + t * 32 * ROWP, pAlo + (size_t)t * 32 * DK);
    #pragma unroll
    for (int t = 0; t < 4; t++)
        cp_async16(sb + soff + (128 + t * 32) * ROWP, pAhi + (size_t)t * 32 * DK);
    #pragma unroll
    for (int t = 0; t < 2; t++)
        cp_async16(sb + soff + (256 + t * 32) * ROWP, pB + (size_t)t * 32 * DK);
    cp_commit();
}

__global__ void __launch_bounds__(256, 2) gemm_kernel(float* __restrict__ out) {
    extern __shared__ __align__(1024) char smem[];
    uint32_t smem_base = smem_to_u32(smem);
    int tid  = threadIdx.x;
    int wid  = tid >> 5, lane = tid & 31;
    int m0   = blockIdx.y * 128, n0 = blockIdx.x * 64;
    int m_w  = (wid >> 1) * 32;          // warp row offset (4 row-groups)
    int n_w  = (wid & 1) * 32;           // warp col offset (2 col-groups)

    // Producer: per-thread fixed (row, 16B-seg) slot
    int r0   = tid >> 3;                 // 0..31
    int cseg = tid & 7;
    uint32_t soff = (uint32_t)(r0 * ROWP + cseg * 16);
    const __half* pAlo = g_Alo + (size_t)(m0 + r0) * DK + cseg * 8;
    const __half* pAhi = g_Ahi + (size_t)(m0 + r0) * DK + cseg * 8;
    const __half* pB   = g_B   + (size_t)(n0 + r0) * DK + cseg * 8;

    // Consumer: per-thread invariant ldmatrix offsets (within a stage)
    uint32_t a_off[2][2];                // [limb][mt]
    #pragma unroll
    for (int L = 0; L < 2; L++)
        #pragma unroll
        for (int mt = 0; mt < 2; mt++)
            a_off[L][mt] = (uint32_t)((L * 128 + m_w + mt * 16 + (lane & 15)) * ROWP
                                      + (lane >> 4) * 16);
    uint32_t b_off[2];                   // p = 0,1 (each ldsm_x4 covers 2 nt)
    #pragma unroll
    for (int p = 0; p < 2; p++)
        b_off[p] = (uint32_t)((256 + n_w + p * 16 + ((lane >> 4) << 3) + (lane & 7)) * ROWP
                              + ((lane >> 3) & 1) * 16);

    float acc[2][2][4][4];               // [limb][mt][nt][frag]
    #pragma unroll
    for (int L = 0; L < 2; L++)
        #pragma unroll
        for (int mt = 0; mt < 2; mt++)
            #pragma unroll
            for (int nt = 0; nt < 4; nt++)
                #pragma unroll
                for (int i = 0; i < 4; i++) acc[L][mt][nt][i] = 0.0f;

    // Prologue: 2-stage pipeline, chunks 0 and 1 in flight.
    issue_chunk_loads(smem_base,           soff, pAlo,      pAhi,      pB);
    issue_chunk_loads(smem_base + STAGE_B, soff, pAlo + 64, pAhi + 64, pB + 64);
    cp_wait<1>();                        // chunk 0 landed
    __syncthreads();

    for (int kk = 0; kk < NCHUNK; kk++) {
        uint32_t sb = smem_base + (kk & 1) * STAGE_B;

        #pragma unroll
        for (int ks = 0; ks < 4; ks++) {       // 4 k16-steps per 64-half chunk
            uint32_t bf[4][2];
            #pragma unroll
            for (int p = 0; p < 2; p++) {
                uint32_t r4[4];
                ldsm_x4(r4, sb + b_off[p] + ks * 32);
                bf[2 * p][0] = r4[0]; bf[2 * p][1] = r4[1];
                bf[2 * p + 1][0] = r4[2]; bf[2 * p + 1][1] = r4[3];
            }
            #pragma unroll
            for (int L = 0; L < 2; L++) {
                uint32_t af[2][4];
                #pragma unroll
                for (int mt = 0; mt < 2; mt++)
                    ldsm_x4(af[mt], sb + a_off[L][mt] + ks * 32);
                #pragma unroll
                for (int mt = 0; mt < 2; mt++)
                    #pragma unroll
                    for (int nt = 0; nt < 4; nt++)
                        mma_16816(acc[L][mt][nt], af[mt], bf[nt]);
            }
        }

        // Stage recycle: all warps finished reading stage kk&1 -> refill it
        // with chunk kk+2; then make chunk kk+1 visible to everyone.
        if (kk + 1 < NCHUNK) {
            __syncthreads();
            if (kk + 2 < NCHUNK) {
                int kh = (kk + 2) * 64;
                issue_chunk_loads(sb, soff, pAlo + kh, pAhi + kh, pB + kh);
                cp_wait<1>();            // retires chunk kk+1's group
            } else {
                cp_wait<0>();
            }
            __syncthreads();
        }
    }

    // Epilogue: combine limbs in int64, wrap to int32, dequantize, write float
    long long mean_abs = g_mean_abs;
    long long sinv = ((long long)1 << 32) / mean_abs;    // fixed_reciprocal
    int g = lane >> 2, t4 = lane & 3;

    #pragma unroll
    for (int mt = 0; mt < 2; mt++) {
        #pragma unroll
        for (int nt = 0; nt < 4; nt++) {
            int n = n0 + n_w + nt * 8 + t4 * 2;
            #pragma unroll
            for (int half = 0; half < 2; half++) {       // c0,c1 then c2,c3
                int m = m0 + m_w + mt * 16 + g + half * 8;
                float2 o2;
                #pragma unroll
                for (int u = 0; u < 2; u++) {
                    long long a = (long long)acc[0][mt][nt][half * 2 + u]
                                + ((long long)acc[1][mt][nt][half * 2 + u] << 11);
                    int a32 = (int)a;                          // int32 wrap
                    long long v = ((long long)a32 * sinv) >> 16;
                    (&o2.x)[u] = (float)v * (1.0f / 65536.0f);
                }
                *reinterpret_cast<float2*>(out + (size_t)m * DN + n) = o2;
            }
        }
    }
}

// ============================================================================
// Launcher (graph-capturable: kernel launches only).
// GEMM is the 4th launch -> lands in the ncu-profiled slot.
// ============================================================================
extern "C" void kernel_launch(void* const* d_in, const int* in_sizes, int n_in,
                              void* d_out, int out_size) {
    const float* x = (const float*)d_in[0];     // [2,2048,4096]
    const float* w = (const float*)d_in[1];     // [4096,4096]
    float* out = (float*)d_out;                 // [2,2048,4096]

    cudaFuncSetAttribute(gemm_kernel, cudaFuncAttributeMaxDynamicSharedMemorySize, SMEM_SZ);

    reduce_partial_kernel<<<256, 256>>>(w);     // launch 1
    actquant_kernel<<<DM, 256>>>(x);            // launch 2
    ternary_kernel<<<NELEM_W / 1024, 256>>>(w); // launch 3 (combine + ternarize)
    dim3 grid(DN / 64, DM / 128);               // 64 x 32 = 2048 CTAs, 2/SM
    gemm_kernel<<<grid, 256, SMEM_SZ>>>(out);   // launch 4 -> profiled
}